// round 12
// baseline (speedup 1.0000x reference)
#include <cuda_runtime.h>
#include <cuda_bf16.h>
#include <math.h>
#include <stdint.h>

// Problem dims (fixed)
#define BSZ  32
#define TLEN 512
#define DIN  512
#define HN   1024
#define G4H  (4*HN)   // 4096

#define WPAD 1028      // W smem row stride (floats) for recurrence
#define HQS  260       // h quarter-row stride (floats); also red batch stride
#define NBLK 128       // persistent grid size (1 CTA/SM)

// GEMM staging (bytes)
#define ABYT 16384     // As: 128 rows x 128B
#define BBYT 17408     // Bs: 32 rows x 544B (136 floats, pad 8)
#define STG  (ABYT + BBYT)

// ---------------- scratch (device globals; no allocation allowed) ----------------
__device__ float g_xg[(size_t)TLEN * BSZ * G4H];   // [T][B][4H]  256 MB
__device__ float g_hseq[(size_t)BSZ * TLEN * HN];  // [B][T][H]    64 MB
__device__ float g_Wp0[(size_t)G4H * HN];          // packed Wh0 (recurrence)
__device__ float g_Wp1[(size_t)G4H * HN];          // packed Wh1
__device__ float g_h[2][BSZ * HN];                 // ping-pong h
__device__ unsigned g_cnt;
__device__ volatile unsigned g_gen;
__device__ float g_Atf[(size_t)16384 * 1024];      // tf32-rounded A   64 MB
__device__ float g_Btf[(size_t)1024 * G4H];        // tf32-rounded W   16 MB

// ---------------- grid-wide barrier ----------------
__device__ __forceinline__ void grid_bar() {
    __threadfence();
    __syncthreads();
    if (threadIdx.x == 0) {
        unsigned my = g_gen;
        if (atomicAdd(&g_cnt, 1u) == (unsigned)(gridDim.x - 1)) {
            g_cnt = 0;
            __threadfence();
            g_gen = my + 1;
        } else {
            while (g_gen == my) { }
        }
        __threadfence();
    }
    __syncthreads();
}

// ---------------- packed dual-fp32 FMA (recurrence) ----------------
__device__ __forceinline__ void ffma2(unsigned long long& d,
                                      unsigned long long a,
                                      unsigned long long b) {
    asm("fma.rn.f32x2 %0, %1, %2, %3;" : "=l"(d) : "l"(a), "l"(b), "l"(d));
}
__device__ __forceinline__ float pairsum(unsigned long long v) {
    return __uint_as_float((unsigned)(v & 0xffffffffull)) +
           __uint_as_float((unsigned)(v >> 32));
}

// ---------------- tf32 + cp.async helpers ----------------
__device__ __forceinline__ unsigned f2tf(float f) {
    unsigned u; asm("cvt.rna.tf32.f32 %0, %1;" : "=r"(u) : "f"(f)); return u;
}
__device__ __forceinline__ void mma_tf32(float* c, const unsigned* a, const unsigned* b) {
    asm volatile(
        "mma.sync.aligned.m16n8k8.row.col.f32.tf32.tf32.f32 "
        "{%0,%1,%2,%3}, {%4,%5,%6,%7}, {%8,%9}, {%0,%1,%2,%3};\n"
        : "+f"(c[0]), "+f"(c[1]), "+f"(c[2]), "+f"(c[3])
        : "r"(a[0]), "r"(a[1]), "r"(a[2]), "r"(a[3]), "r"(b[0]), "r"(b[1]));
}
__device__ __forceinline__ uint32_t smem_u32(const void* p) {
    uint32_t a;
    asm("{ .reg .u64 t; cvta.to.shared.u64 t, %1; cvt.u32.u64 %0, t; }"
        : "=r"(a) : "l"(p));
    return a;
}
__device__ __forceinline__ void cp16(uint32_t d, const void* s) {
    asm volatile("cp.async.cg.shared.global [%0], [%1], 16;" :: "r"(d), "l"(s));
}
__device__ __forceinline__ void cp_commit() {
    asm volatile("cp.async.commit_group;" ::: "memory");
}

// ---------------- prep: round fp32 -> tf32 ----------------
__global__ void cvt_tf32_kernel(const float* __restrict__ in,
                                float* __restrict__ out, int n4) {
    int i = blockIdx.x * blockDim.x + threadIdx.x;
    if (i >= n4) return;
    float4 v = *(const float4*)(in + (size_t)i * 4);
    v.x = __uint_as_float(f2tf(v.x));
    v.y = __uint_as_float(f2tf(v.y));
    v.z = __uint_as_float(f2tf(v.z));
    v.w = __uint_as_float(f2tf(v.w));
    *(float4*)(out + (size_t)i * 4) = v;
}

// ---------------- pack Wh [K=1024][4096] -> Wp[row][k] (recurrence) ----------------
__global__ void pack_wh_kernel(const float* __restrict__ Wh, float* __restrict__ Wp) {
    __shared__ float tile[32][33];
    const int c0 = blockIdx.x * 32;
    const int k0 = blockIdx.y * 32;
    const int tx = threadIdx.x, ty = threadIdx.y;
#pragma unroll
    for (int i = 0; i < 32; i += 8)
        tile[ty + i][tx] = Wh[(size_t)(k0 + ty + i) * G4H + c0 + tx];
    __syncthreads();
#pragma unroll
    for (int i = 0; i < 32; i += 8) {
        int c  = c0 + ty + i;
        int g  = c >> 10;
        int r  = c & (HN - 1);
        int row = ((r >> 3) << 5) + (g << 3) + (r & 7);
        Wp[(size_t)row * HN + k0 + tx] = tile[tx][ty + i];
    }
}

// ---------------- tf32 mma GEMM (unchanged from R11, passing) ----------------
__global__ void __launch_bounds__(256, 2) gemm_xg_cp(
    const float* __restrict__ A, const float* __restrict__ Bw,
    const float* __restrict__ bias, float* __restrict__ C, int K)
{
    extern __shared__ char gsm[];
    const uint32_t sb = smem_u32(gsm);

    const int tid = threadIdx.x;
    const int bx = blockIdx.x;
    const int by = blockIdx.y;
    const int wid = tid >> 5;
    const int lane = tid & 31;
    const int g = lane >> 2, tg = lane & 3;
    const int wm = wid & 1, wn = wid >> 1;
    const int m0w = wm * 64, n0w = wn * 32;
    const int KT = K >> 5;

    const int aR = tid >> 3, aKc = tid & 7;
    const int bR = tid >> 5, bNc = tid & 31;

    float acc[4][4][4];
#pragma unroll
    for (int a = 0; a < 4; a++)
#pragma unroll
        for (int b = 0; b < 4; b++)
#pragma unroll
            for (int cix = 0; cix < 4; cix++) acc[a][b][cix] = 0.f;

    auto issue = [&](int kt, int buf) {
        const uint32_t as = sb + buf * STG;
        const uint32_t bs = as + ABYT;
#pragma unroll
        for (int it = 0; it < 4; it++) {
            int row = it * 32 + aR;
            uint32_t doff = row * 128 + ((aKc * 16) ^ ((row & 7) << 4));
            cp16(as + doff, A + (size_t)(by * 128 + row) * K + kt * 32 + aKc * 4);
        }
#pragma unroll
        for (int it = 0; it < 4; it++) {
            int kr = it * 8 + bR;
            cp16(bs + kr * 544 + bNc * 16,
                 Bw + (size_t)(kt * 32 + kr) * G4H + bx * 128 + bNc * 4);
        }
        cp_commit();
    };

    issue(0, 0);
    for (int kt = 0; kt < KT; kt++) {
        const int buf = kt & 1;
        if (kt + 1 < KT) {
            issue(kt + 1, (kt + 1) & 1);
            asm volatile("cp.async.wait_group 1;" ::: "memory");
        } else {
            asm volatile("cp.async.wait_group 0;" ::: "memory");
        }
        __syncthreads();

        const unsigned* As = (const unsigned*)(gsm + buf * STG);
        const unsigned* Bs = (const unsigned*)(gsm + buf * STG + ABYT);
#pragma unroll
        for (int s = 0; s < 4; s++) {
            unsigned af[4][4], bf[4][2];
            const int c0 = (8 * s + tg) ^ (g << 2);
            const int c1 = c0 ^ 4;
#pragma unroll
            for (int mb = 0; mb < 4; mb++) {
                int m = m0w + mb * 16 + g;
                af[mb][0] = As[m * 32 + c0];
                af[mb][1] = As[(m + 8) * 32 + c0];
                af[mb][2] = As[m * 32 + c1];
                af[mb][3] = As[(m + 8) * 32 + c1];
            }
#pragma unroll
            for (int nb = 0; nb < 4; nb++) {
                bf[nb][0] = Bs[(8 * s + tg) * 136 + n0w + nb * 8 + g];
                bf[nb][1] = Bs[(8 * s + tg + 4) * 136 + n0w + nb * 8 + g];
            }
#pragma unroll
            for (int mb = 0; mb < 4; mb++)
#pragma unroll
                for (int nb = 0; nb < 4; nb++)
                    mma_tf32(acc[mb][nb], af[mb], bf[nb]);
        }
        __syncthreads();
    }

#pragma unroll
    for (int mb = 0; mb < 4; mb++) {
        int m1 = by * 128 + m0w + mb * 16 + g;
        int m2 = m1 + 8;
        size_t r1 = (size_t)(((m1 & 511) << 5) + (m1 >> 9)) * G4H;
        size_t r2 = (size_t)(((m2 & 511) << 5) + (m2 >> 9)) * G4H;
#pragma unroll
        for (int nb = 0; nb < 4; nb++) {
            int n = bx * 128 + n0w + nb * 8 + 2 * tg;
            float2 bb = *(const float2*)(bias + n);
            float2 o1 = { acc[mb][nb][0] + bb.x, acc[mb][nb][1] + bb.y };
            float2 o2 = { acc[mb][nb][2] + bb.x, acc[mb][nb][3] + bb.y };
            *(float2*)(C + r1 + n) = o1;
            *(float2*)(C + r2 + n) = o2;
        }
    }
}

// ---------------- persistent LSTM layer: 512 threads, 16 warps ----------------
// Block nb owns 8 n-cols (32 gate-cols = packed W rows nb*32..+32).
// Warp wq: ks = wq>>1 (k-slice of 32 per quarter), bh = wq&1 (batch half).
// Lane jj = gate-col; acc2[16] covers batches bh*16..+16 as (k-even,k-odd) pairs.
// Reduction: red[b][ks*32+gc] aliased on hq0 (stride HQS), one sync, epilogue
// (first 256 threads) sums 8 k-slices per gate.
extern __shared__ float s_mem[];
__global__ void __launch_bounds__(512, 1) lstm_layer_persistent(
    const float* __restrict__ xg, const float* __restrict__ Wp,
    float* __restrict__ hA, float* __restrict__ hB, float* __restrict__ outb)
{
    const int tid = threadIdx.x;
    const int jj  = tid & 31;
    const int wq  = tid >> 5;        // 0..15
    const int ks  = wq >> 1;         // 0..7
    const int bh  = wq & 1;          // 0..1
    const int b0  = bh * 16;
    const int nb  = blockIdx.x;

    float* Wsm = s_mem;                       // 32 x WPAD
    float* hq0 = s_mem + 32 * WPAD;           // 32 x HQS (quarter ping)
    float* hq1 = hq0 + 32 * HQS;              // 32 x HQS (quarter pong)
    float* red = hq0;                         // [32][HQS] alias: red[b*HQS + ks*32 + gc]

    // ---- load this block's W slice into smem (once per layer) ----
    {
        const float4* Wg = (const float4*)(Wp + (size_t)nb * 32 * HN);
#pragma unroll
        for (int it = 0; it < 16; it++) {
            int i4  = it * 512 + tid;         // 0..8191
            int row = i4 >> 8;
            int col = i4 & 255;
            *(float4*)(Wsm + (size_t)row * WPAD + col * 4) = Wg[i4];
        }
    }

    const int nl  = tid & 7;
    const int myn = nb * 8 + nl;              // epilogue lane's output col
    const int myb = (tid >> 3) & 31;          // epilogue lane's batch (tid<256)
    if (tid < 256) hA[myb * HN + myn] = 0.f;
    float creg = 0.f;
    __syncthreads();
    grid_bar();

    for (int t = 0; t < TLEN; t++) {
        const float* h_in  = (t & 1) ? hB : hA;
        float*       h_out = (t & 1) ? hA : hB;
        const float* xg_t  = xg + (size_t)t * BSZ * G4H;

        // epilogue lanes prefetch their 4 gate inputs (latency hidden by k-loop)
        float xvi = 0.f, xvf = 0.f, xvg = 0.f, xvo = 0.f;
        if (tid < 256) {
            const float* xp = xg_t + (size_t)myb * G4H + myn;
            xvi = xp[0];
            xvf = xp[HN];
            xvg = xp[2 * HN];
            xvo = xp[3 * HN];
        }

        unsigned long long acc2[16];
#pragma unroll
        for (int b = 0; b < 16; b++) acc2[b] = 0ull;

        // prefetch quarter 0 (L2 reads: h written by other SMs)
        float4 p[4];
#pragma unroll
        for (int i = 0; i < 4; i++) {
            int idx = i * 512 + tid;          // 0..2047 float4s
            int b = idx >> 6, k4 = idx & 63;
            p[i] = __ldcg((const float4*)&h_in[(size_t)b * HN + k4 * 4]);
        }

#pragma unroll
        for (int q = 0; q < 4; q++) {
            float* hs = (q & 1) ? hq1 : hq0;
#pragma unroll
            for (int i = 0; i < 4; i++) {
                int idx = i * 512 + tid;
                int b = idx >> 6, k4 = idx & 63;
                *(float4*)&hs[b * HQS + k4 * 4] = p[i];
            }
            __syncthreads();                  // single sync per quarter (see proof in notes)
            if (q < 3) {
#pragma unroll
                for (int i = 0; i < 4; i++) {
                    int idx = i * 512 + tid;
                    int b = idx >> 6, k4 = idx & 63;
                    p[i] = __ldcg((const float4*)
                        &h_in[(size_t)b * HN + (q + 1) * 256 + k4 * 4]);
                }
            }
            const ulonglong2* Wk = (const ulonglong2*)
                (Wsm + (size_t)jj * WPAD + q * 256 + ks * 32);
            const char* hbase = (const char*)(hs + (size_t)b0 * HQS + ks * 32);
#pragma unroll
            for (int g = 0; g < 8; g++) {
                ulonglong2 wv = Wk[g];
                const char* hp = hbase + g * 16;
#pragma unroll
                for (int bb = 0; bb < 16; bb++) {
                    ulonglong2 hv = *(const ulonglong2*)(hp + bb * (HQS * 4));
                    ffma2(acc2[bb], wv.x, hv.x);
                    ffma2(acc2[bb], wv.y, hv.y);
                }
            }
        }

        // single-phase reduction store: red (hq0) is free (last compute on hq0 was q=2,
        // finished before the q=3 sync; q=3 compute reads hq1 only)
#pragma unroll
        for (int bb = 0; bb < 16; bb++)
            red[(size_t)(b0 + bb) * HQS + ks * 32 + jj] = pairsum(acc2[bb]);
        __syncthreads();

        if (tid < 256) {
            float gi = xvi, gf = xvf, gg = xvg, go = xvo;
#pragma unroll
            for (int s = 0; s < 8; s++) {
                const float* rp = &red[(size_t)myb * HQS + s * 32];
                gi += rp[nl];
                gf += rp[8 + nl];
                gg += rp[16 + nl];
                go += rp[24 + nl];
            }
            float si = 1.f / (1.f + expf(-gi));
            float sf = 1.f / (1.f + expf(-gf));
            float so = 1.f / (1.f + expf(-go));
            creg = sf * creg + si * tanhf(gg);
            float hv = so * tanhf(creg);
            h_out[(size_t)myb * HN + myn] = hv;
            outb[(size_t)myb * (TLEN * HN) + (size_t)t * HN + myn] = hv;
        }

        grid_bar();
    }
}

// ---------------- driver ----------------
extern "C" void kernel_launch(void* const* d_in, const int* in_sizes, int n_in,
                              void* d_out, int out_size) {
    const float* x   = (const float*)d_in[0];
    const float* Wx0 = (const float*)d_in[1];
    const float* Wh0 = (const float*)d_in[2];
    const float* b0  = (const float*)d_in[3];
    const float* Wx1 = (const float*)d_in[4];
    const float* Wh1 = (const float*)d_in[5];
    const float* b1  = (const float*)d_in[6];
    float* out = (float*)d_out;

    float *xg, *hseq, *wp0, *wp1, *hbuf, *atf, *btf;
    cudaGetSymbolAddress((void**)&xg,   g_xg);
    cudaGetSymbolAddress((void**)&hseq, g_hseq);
    cudaGetSymbolAddress((void**)&wp0,  g_Wp0);
    cudaGetSymbolAddress((void**)&wp1,  g_Wp1);
    cudaGetSymbolAddress((void**)&hbuf, g_h);
    cudaGetSymbolAddress((void**)&atf,  g_Atf);
    cudaGetSymbolAddress((void**)&btf,  g_Btf);

    const int SMEMB = (32 * WPAD + 2 * 32 * HQS) * (int)sizeof(float);
    cudaFuncSetAttribute(lstm_layer_persistent,
                         cudaFuncAttributeMaxDynamicSharedMemorySize, SMEMB);
    const int GSMEM = 2 * STG;
    cudaFuncSetAttribute(gemm_xg_cp,
                         cudaFuncAttributeMaxDynamicSharedMemorySize, GSMEM);

    const dim3 tpb(32, 8);

    // keep the capture-friendly order: cvtA(1), cvtW(2), pack0(3), gemm0(4), ...
    cvt_tf32_kernel<<<(16384 * DIN / 4 + 255) / 256, 256>>>(x, atf, 16384 * DIN / 4);
    cvt_tf32_kernel<<<(DIN * G4H / 4 + 255) / 256, 256>>>(Wx0, btf, DIN * G4H / 4);
    pack_wh_kernel<<<dim3(G4H / 32, HN / 32), tpb>>>(Wh0, wp0);
    gemm_xg_cp<<<dim3(G4H / 128, 16384 / 128), 256, GSMEM>>>(atf, btf, b0, xg, DIN);
    pack_wh_kernel<<<dim3(G4H / 32, HN / 32), tpb>>>(Wh1, wp1);
    lstm_layer_persistent<<<NBLK, 512, SMEMB>>>(
        xg, wp0, hbuf, hbuf + BSZ * HN, hseq);

    // ---- layer 1 ----
    cvt_tf32_kernel<<<(16384 * HN / 4 + 255) / 256, 256>>>(hseq, atf, 16384 * HN / 4);
    cvt_tf32_kernel<<<(HN * G4H / 4 + 255) / 256, 256>>>(Wx1, btf, HN * G4H / 4);
    gemm_xg_cp<<<dim3(G4H / 128, 16384 / 128), 256, GSMEM>>>(atf, btf, b1, xg, HN);
    lstm_layer_persistent<<<NBLK, 512, SMEMB>>>(
        xg, wp1, hbuf, hbuf + BSZ * HN, out);
}